// round 8
// baseline (speedup 1.0000x reference)
#include <cuda_runtime.h>
#include <cuda_bf16.h>
#include <cstdint>
#include <math.h>

// out = GELU_exact(x @ W.T + b)
// R8: exact int8 fixed-point split GEMM via mma.sync.m16n8k32.s8 (k32 -> half the
// instruction count of the bf16 k16 3-term scheme). Per-row quantization:
//   x ~= sA[r]*(128*h + l), W ~= sB[o]*(128*h' + l'),  h,l int8 (|h|<=127,|l|<=64)
//   x.w = sA*sB*(16384*HH + 128*(H.L' + L.H'))   (L.L' dropped, ~1e-4 rel)
// Integer accumulation is exact; HH,CR < 2^24 so fp32 conversion is exact.

#define NN 8192
#define KK 512
#define OO 512

#define BM 128
#define BN 128
#define BK 64                    // int8 elems per k-tile (64 bytes/row)
#define NKT (KK / BK)            // 8
#define THREADS 512

// stage: Ah[128x64] 8K | Al 8K | Bh 8K | Bl 8K
#define ST_AL  8192
#define ST_BH  16384
#define ST_BL  24576
#define STAGE  32768
#define NSTAGE 3
#define SMEM_TOTAL (NSTAGE * STAGE)   // 96 KB

// quantized operand buffers + scales
__device__ __align__(128) uint8_t g_ah[NN * KK];
__device__ __align__(128) uint8_t g_al[NN * KK];
__device__ __align__(128) uint8_t g_bh[OO * KK];
__device__ __align__(128) uint8_t g_bl[OO * KK];
__device__ float g_sa[NN];
__device__ float g_sb[OO];

__device__ __forceinline__ uint32_t smem_u32(const void* p) {
    uint32_t a;
    asm("{ .reg .u64 t; cvta.to.shared.u64 t, %1; cvt.u32.u64 %0, t; }" : "=r"(a) : "l"(p));
    return a;
}

#define CP16(dst, src) \
    asm volatile("cp.async.cg.shared.global [%0], [%1], 16;" :: "r"(dst), "l"(src) : "memory")
#define CP_COMMIT() asm volatile("cp.async.commit_group;" ::: "memory")
#define CP_WAIT1()  asm volatile("cp.async.wait_group 1;" ::: "memory")

__device__ __forceinline__ void ldm4(uint32_t* r, uint32_t addr) {
    asm volatile("ldmatrix.sync.aligned.m8n8.x4.shared.b16 {%0,%1,%2,%3}, [%4];"
                 : "=r"(r[0]), "=r"(r[1]), "=r"(r[2]), "=r"(r[3]) : "r"(addr));
}

__device__ __forceinline__ void mma_s8(int* d, const uint32_t* a, const uint32_t* b) {
    asm volatile(
        "mma.sync.aligned.m16n8k32.row.col.s32.s8.s8.s32 "
        "{%0,%1,%2,%3}, {%4,%5,%6,%7}, {%8,%9}, {%0,%1,%2,%3};"
        : "+r"(d[0]), "+r"(d[1]), "+r"(d[2]), "+r"(d[3])
        : "r"(a[0]), "r"(a[1]), "r"(a[2]), "r"(a[3]), "r"(b[0]), "r"(b[1]));
}

// swizzled byte offset inside a tile: row r (64B rows = 4 x 16B chunks), chunk c
__device__ __forceinline__ uint32_t swz(int r, int c) {
    return (uint32_t)(r * 64 + ((c ^ ((r >> 1) & 3)) << 4));
}

// A&S 7.1.26 erf (abs err 1.5e-7)
__device__ __forceinline__ float gelu_f(float h) {
    float s = h * 0.70710678118654752f;
    float a = fabsf(s);
    float t = __frcp_rn(fmaf(0.3275911f, a, 1.0f));
    float p = fmaf(fmaf(fmaf(fmaf(1.061405429f, t, -1.453152027f), t, 1.421413741f),
                        t, -0.284496736f), t, 0.254829592f) * t;
    float e = __expf(-a * a);
    float erfv = fmaf(-p, e, 1.0f);
    erfv = copysignf(erfv, s);
    return 0.5f * h * (1.0f + erfv);
}

// ---------------- quantize kernel: one block per row ----------------
__global__ __launch_bounds__(128) void quant_kernel(const float* __restrict__ x,
                                                    const float* __restrict__ W) {
    const int row = blockIdx.x;
    const int t = threadIdx.x, l = t & 31, w = t >> 5;
    const float* src;
    uint32_t *dh, *dl;
    float* ds;
    if (row < NN) {
        src = x + (size_t)row * KK;
        dh = (uint32_t*)(g_ah + (size_t)row * KK);
        dl = (uint32_t*)(g_al + (size_t)row * KK);
        ds = g_sa + row;
    } else {
        const int r = row - NN;
        src = W + (size_t)r * KK;
        dh = (uint32_t*)(g_bh + (size_t)r * KK);
        dl = (uint32_t*)(g_bl + (size_t)r * KK);
        ds = g_sb + r;
    }
    float4 v = ((const float4*)src)[t];
    float m = fmaxf(fmaxf(fabsf(v.x), fabsf(v.y)), fmaxf(fabsf(v.z), fabsf(v.w)));
#pragma unroll
    for (int o = 16; o; o >>= 1) m = fmaxf(m, __shfl_xor_sync(0xFFFFFFFFu, m, o));
    __shared__ float sm[4];
    if (l == 0) sm[w] = m;
    __syncthreads();
    float mx = fmaxf(fmaxf(sm[0], sm[1]), fmaxf(sm[2], sm[3]));
    mx = fmaxf(mx, 1e-30f);
    const float s = 16256.0f / mx;
    if (t == 0) *ds = mx * (1.0f / 16256.0f);

    float f[4] = {v.x, v.y, v.z, v.w};
    uint32_t hp = 0, lp = 0;
#pragma unroll
    for (int j = 0; j < 4; j++) {
        float X = f[j] * s;
        int h = __float2int_rn(X * (1.0f / 128.0f));
        int lo = __float2int_rn(fmaf(-128.0f, (float)h, X));
        hp |= (uint32_t)(h & 0xFF) << (8 * j);
        lp |= (uint32_t)(lo & 0xFF) << (8 * j);
    }
    dh[t] = hp;
    dl[t] = lp;
}

// ---------------- main GEMM kernel ----------------
__device__ __forceinline__ void load_stage(uint32_t S, int buf, int kt, int mb, int nb, int tid) {
    const uint32_t st = S + buf * STAGE;
    const int kbase = kt * BK;
    const int r = tid >> 2, c = tid & 3;          // 128 rows x 4 x 16B chunks
    const uint32_t sw = swz(r, c);
    {
        size_t so = (size_t)(mb * BM + r) * KK + kbase + c * 16;
        CP16(st + sw, g_ah + so);
        CP16(st + ST_AL + sw, g_al + so);
    }
    {
        size_t so = (size_t)(nb * BN + r) * KK + kbase + c * 16;
        CP16(st + ST_BH + sw, g_bh + so);
        CP16(st + ST_BL + sw, g_bl + so);
    }
    CP_COMMIT();
}

__global__ __launch_bounds__(THREADS, 1)
void gemm_s8_kernel(const float* __restrict__ bias, float* __restrict__ C) {
    extern __shared__ uint8_t smem[];
    const uint32_t S = smem_u32(smem);
    const int tid = threadIdx.x;
    const int l = tid & 31, wid = tid >> 5;
    const int mwarp = wid & 3;   // 4 M-warps of 32 rows
    const int nwarp = wid >> 2;  // 4 N-warps of 32 cols
    const int mb = blockIdx.x, nb = blockIdx.y;

    // ldmatrix lane addressing (same proven maps; rows now 64B of int8)
    const int a_r = ((l >> 3) & 1) * 8 + (l & 7);
    const int a_cs = (l >> 4) & 1;
    const int b_n = ((l >> 4) & 1) * 8 + (l & 7);
    const int b_cs = (l >> 3) & 1;

    int accH[2][4][4], accC[2][4][4];
#pragma unroll
    for (int i = 0; i < 2; i++)
#pragma unroll
        for (int j = 0; j < 4; j++)
#pragma unroll
            for (int k = 0; k < 4; k++) { accH[i][j][k] = 0; accC[i][j][k] = 0; }

    load_stage(S, 0, 0, mb, nb, tid);
    load_stage(S, 1, 1, mb, nb, tid);

    for (int kt = 0; kt < NKT; kt++) {
        CP_WAIT1();
        __syncthreads();
        if (kt + 2 < NKT) load_stage(S, (kt + 2) % NSTAGE, kt + 2, mb, nb, tid);
        const uint32_t stg = S + (kt % NSTAGE) * STAGE;

#pragma unroll
        for (int ks = 0; ks < 2; ks++) {
            const int c0 = ks * 2;   // 32-int8 half of the 64-int8 k-tile
            uint32_t Bh[8], Ah[8], Bl[8], Al[8];
#pragma unroll
            for (int nf2 = 0; nf2 < 2; nf2++)
                ldm4(&Bh[nf2 * 4], stg + ST_BH + swz(nwarp * 32 + nf2 * 16 + b_n, c0 + b_cs));
#pragma unroll
            for (int mf = 0; mf < 2; mf++)
                ldm4(&Ah[mf * 4], stg + swz(mwarp * 32 + mf * 16 + a_r, c0 + a_cs));
            // HH
#pragma unroll
            for (int mf = 0; mf < 2; mf++)
#pragma unroll
                for (int nf = 0; nf < 4; nf++)
                    mma_s8(accH[mf][nf], &Ah[mf * 4], &Bh[nf * 2]);
            // CR += H * L'
#pragma unroll
            for (int nf2 = 0; nf2 < 2; nf2++)
                ldm4(&Bl[nf2 * 4], stg + ST_BL + swz(nwarp * 32 + nf2 * 16 + b_n, c0 + b_cs));
#pragma unroll
            for (int mf = 0; mf < 2; mf++)
#pragma unroll
                for (int nf = 0; nf < 4; nf++)
                    mma_s8(accC[mf][nf], &Ah[mf * 4], &Bl[nf * 2]);
            // CR += L * H'
#pragma unroll
            for (int mf = 0; mf < 2; mf++)
                ldm4(&Al[mf * 4], stg + ST_AL + swz(mwarp * 32 + mf * 16 + a_r, c0 + a_cs));
#pragma unroll
            for (int mf = 0; mf < 2; mf++)
#pragma unroll
                for (int nf = 0; nf < 4; nf++)
                    mma_s8(accC[mf][nf], &Al[mf * 4], &Bh[nf * 2]);
        }
    }

    // epilogue: dequant + bias + GELU
#pragma unroll
    for (int mf = 0; mf < 2; mf++) {
#pragma unroll
        for (int nf = 0; nf < 4; nf++) {
            int m0 = mb * BM + mwarp * 32 + mf * 16 + (l >> 2);
            int n0 = nb * BN + nwarp * 32 + nf * 8 + 2 * (l & 3);
            float sa0 = __ldg(&g_sa[m0]);
            float sa1 = __ldg(&g_sa[m0 + 8]);
            float sb0 = __ldg(&g_sb[n0]);
            float sb1 = __ldg(&g_sb[n0 + 1]);
            float b0 = __ldg(&bias[n0]);
            float b1 = __ldg(&bias[n0 + 1]);
            const int* H = accH[mf][nf];
            const int* R = accC[mf][nf];
            float2 v0, v1;
            v0.x = gelu_f(fmaf(sa0 * sb0,
                               fmaf(16384.0f, (float)H[0], 128.0f * (float)R[0]), b0));
            v0.y = gelu_f(fmaf(sa0 * sb1,
                               fmaf(16384.0f, (float)H[1], 128.0f * (float)R[1]), b1));
            v1.x = gelu_f(fmaf(sa1 * sb0,
                               fmaf(16384.0f, (float)H[2], 128.0f * (float)R[2]), b0));
            v1.y = gelu_f(fmaf(sa1 * sb1,
                               fmaf(16384.0f, (float)H[3], 128.0f * (float)R[3]), b1));
            *(float2*)&C[(size_t)m0 * OO + n0] = v0;
            *(float2*)&C[(size_t)(m0 + 8) * OO + n0] = v1;
        }
    }
}

// ---------------- launch ----------------
extern "C" void kernel_launch(void* const* d_in, const int* in_sizes, int n_in,
                              void* d_out, int out_size) {
    const float* x = (const float*)d_in[0];
    const float* W = (const float*)d_in[2];
    const float* b = (const float*)d_in[3];
    float* out = (float*)d_out;

    cudaFuncSetAttribute(gemm_s8_kernel,
                         cudaFuncAttributeMaxDynamicSharedMemorySize, SMEM_TOTAL);

    quant_kernel<<<NN + OO, 128>>>(x, W);   // one block per row (8704 blocks)

    dim3 grid(NN / BM, OO / BN);  // (64, 4) = 256 CTAs
    gemm_s8_kernel<<<grid, THREADS, SMEM_TOTAL>>>(b, out);
}

// round 9
// speedup vs baseline: 2.0792x; 2.0792x over previous
#include <cuda_runtime.h>
#include <cuda_fp16.h>
#include <cstdint>
#include <math.h>

// out = GELU_exact(x @ W.T + b)
// R9: single-term fp16 mma.sync GEMM (m16n8k16.f32.f16.f16.f32).
// x,W rounded once to fp16 (rne) in a pack pass; error = input quantization
// only (~2.5e-4 rel, threshold 1e-3). 3x fewer MMA instructions than the
// bf16 3-term split -> mma.sync instruction-cost floor drops 3x.

#define NN 8192
#define KK 512
#define OO 512

#define BM 128
#define BN 128
#define BK 64                    // fp16 elems per k-tile (128 B/row)
#define NKT (KK / BK)            // 8
#define THREADS 512

// stage: A[128x64 fp16] 16K | B[128x64 fp16] 16K
#define ST_B   16384
#define STAGE  32768
#define NSTAGE 3
#define SMEM_TOTAL (NSTAGE * STAGE)   // 96 KB

__device__ __align__(128) __half g_xh[NN * KK];   // 8 MB
__device__ __align__(128) __half g_wh[OO * KK];   // 0.5 MB

__device__ __forceinline__ uint32_t smem_u32(const void* p) {
    uint32_t a;
    asm("{ .reg .u64 t; cvta.to.shared.u64 t, %1; cvt.u32.u64 %0, t; }" : "=r"(a) : "l"(p));
    return a;
}

#define CP16(dst, src) \
    asm volatile("cp.async.cg.shared.global [%0], [%1], 16;" :: "r"(dst), "l"(src) : "memory")
#define CP_COMMIT() asm volatile("cp.async.commit_group;" ::: "memory")
#define CP_WAIT1()  asm volatile("cp.async.wait_group 1;" ::: "memory")

__device__ __forceinline__ void ldm4(uint32_t* r, uint32_t addr) {
    asm volatile("ldmatrix.sync.aligned.m8n8.x4.shared.b16 {%0,%1,%2,%3}, [%4];"
                 : "=r"(r[0]), "=r"(r[1]), "=r"(r[2]), "=r"(r[3]) : "r"(addr));
}

__device__ __forceinline__ void mma_f16(float* d, const uint32_t* a, const uint32_t* b) {
    asm volatile(
        "mma.sync.aligned.m16n8k16.row.col.f32.f16.f16.f32 "
        "{%0,%1,%2,%3}, {%4,%5,%6,%7}, {%8,%9}, {%0,%1,%2,%3};"
        : "+f"(d[0]), "+f"(d[1]), "+f"(d[2]), "+f"(d[3])
        : "r"(a[0]), "r"(a[1]), "r"(a[2]), "r"(a[3]), "r"(b[0]), "r"(b[1]));
}

// swizzled byte offset in a 128B-row tile: row r, 16B-chunk c (0..7)
__device__ __forceinline__ uint32_t swz8(int r, int c) {
    return (uint32_t)(r * 128 + (((c ^ (r & 7))) << 4));
}

// A&S 7.1.26 erf (abs err 1.5e-7)
__device__ __forceinline__ float gelu_f(float h) {
    float s = h * 0.70710678118654752f;
    float a = fabsf(s);
    float t = __frcp_rn(fmaf(0.3275911f, a, 1.0f));
    float p = fmaf(fmaf(fmaf(fmaf(1.061405429f, t, -1.453152027f), t, 1.421413741f),
                        t, -0.284496736f), t, 0.254829592f) * t;
    float e = __expf(-a * a);
    float erfv = fmaf(-p, e, 1.0f);
    erfv = copysignf(erfv, s);
    return 0.5f * h * (1.0f + erfv);
}

// ---------------- pack kernel: f32 -> fp16 (rne) ----------------
__global__ __launch_bounds__(256) void pack_kernel(const float* __restrict__ x,
                                                   const float* __restrict__ W) {
    const int g = blockIdx.x * 256 + threadIdx.x;
    const int A_GROUPS = NN * (KK / 8);   // 524288
    const float* src;
    __half* dst;
    if (g < A_GROUPS) {
        src = x + (size_t)g * 8;
        dst = g_xh + (size_t)g * 8;
    } else {
        size_t g2 = (size_t)(g - A_GROUPS);
        src = W + g2 * 8;
        dst = g_wh + g2 * 8;
    }
    float4 v0 = *(const float4*)src;
    float4 v1 = *(const float4*)(src + 4);
    uint32_t o[4];
    o[0] = (uint32_t)__half_as_ushort(__float2half_rn(v0.x)) |
           ((uint32_t)__half_as_ushort(__float2half_rn(v0.y)) << 16);
    o[1] = (uint32_t)__half_as_ushort(__float2half_rn(v0.z)) |
           ((uint32_t)__half_as_ushort(__float2half_rn(v0.w)) << 16);
    o[2] = (uint32_t)__half_as_ushort(__float2half_rn(v1.x)) |
           ((uint32_t)__half_as_ushort(__float2half_rn(v1.y)) << 16);
    o[3] = (uint32_t)__half_as_ushort(__float2half_rn(v1.z)) |
           ((uint32_t)__half_as_ushort(__float2half_rn(v1.w)) << 16);
    *(uint4*)dst = make_uint4(o[0], o[1], o[2], o[3]);
}

// ---------------- main GEMM kernel ----------------
__device__ __forceinline__ void load_stage(uint32_t S, int buf, int kt, int mb, int nb, int tid) {
    const uint32_t st = S + buf * STAGE;
    const int kbase = kt * BK;
    // A: 1024 chunk slots (128 rows x 8 chunks); 512 threads -> 2 each
#pragma unroll
    for (int j = 0; j < 2; j++) {
        int q = tid + j * 512;
        int r = q >> 3, c = q & 7;
        size_t so = (size_t)(mb * BM + r) * KK + kbase + c * 8;
        CP16(st + swz8(r, c), (const uint8_t*)(g_xh + so));
    }
    // B: 1024 chunk slots
#pragma unroll
    for (int j = 0; j < 2; j++) {
        int q = tid + j * 512;
        int r = q >> 3, c = q & 7;
        size_t so = (size_t)(nb * BN + r) * KK + kbase + c * 8;
        CP16(st + ST_B + swz8(r, c), (const uint8_t*)(g_wh + so));
    }
    CP_COMMIT();
}

__global__ __launch_bounds__(THREADS, 2)
void gemm_f16_kernel(const float* __restrict__ bias, float* __restrict__ C) {
    extern __shared__ uint8_t smem[];
    const uint32_t S = smem_u32(smem);
    const int tid = threadIdx.x;
    const int l = tid & 31, wid = tid >> 5;
    const int mwarp = wid & 3;   // 4 M-warps of 32 rows
    const int nwarp = wid >> 2;  // 4 N-warps of 32 cols
    const int mb = blockIdx.x, nb = blockIdx.y;

    // ldmatrix lane maps (proven in R4-R7; rows now 128B wide)
    const int a_r = ((l >> 3) & 1) * 8 + (l & 7);
    const int a_cs = (l >> 4) & 1;
    const int b_n = ((l >> 4) & 1) * 8 + (l & 7);
    const int b_cs = (l >> 3) & 1;

    float acc[2][4][4];
#pragma unroll
    for (int i = 0; i < 2; i++)
#pragma unroll
        for (int j = 0; j < 4; j++)
#pragma unroll
            for (int k = 0; k < 4; k++) acc[i][j][k] = 0.0f;

    load_stage(S, 0, 0, mb, nb, tid);
    load_stage(S, 1, 1, mb, nb, tid);

    for (int kt = 0; kt < NKT; kt++) {
        CP_WAIT1();
        __syncthreads();
        if (kt + 2 < NKT) load_stage(S, (kt + 2) % NSTAGE, kt + 2, mb, nb, tid);
        const uint32_t stg = S + (kt % NSTAGE) * STAGE;

#pragma unroll
        for (int ks = 0; ks < 4; ks++) {           // 4 k16 slices in BK=64
            const int c0 = ks * 2;                 // 16B-chunk base of this k16
            uint32_t A[2][4], B[8];
#pragma unroll
            for (int nf2 = 0; nf2 < 2; nf2++)
                ldm4(&B[nf2 * 4], stg + ST_B + swz8(nwarp * 32 + nf2 * 16 + b_n, c0 + b_cs));
#pragma unroll
            for (int mf = 0; mf < 2; mf++)
                ldm4(A[mf], stg + swz8(mwarp * 32 + mf * 16 + a_r, c0 + a_cs));
#pragma unroll
            for (int mf = 0; mf < 2; mf++)
#pragma unroll
                for (int nf = 0; nf < 4; nf++)
                    mma_f16(acc[mf][nf], A[mf], &B[nf * 2]);
        }
    }

    // epilogue: bias + GELU
#pragma unroll
    for (int mf = 0; mf < 2; mf++) {
#pragma unroll
        for (int nf = 0; nf < 4; nf++) {
            int m0 = mb * BM + mwarp * 32 + mf * 16 + (l >> 2);
            int n0 = nb * BN + nwarp * 32 + nf * 8 + 2 * (l & 3);
            float b0 = __ldg(&bias[n0]);
            float b1 = __ldg(&bias[n0 + 1]);
            float2 v0, v1;
            v0.x = gelu_f(acc[mf][nf][0] + b0);
            v0.y = gelu_f(acc[mf][nf][1] + b1);
            v1.x = gelu_f(acc[mf][nf][2] + b0);
            v1.y = gelu_f(acc[mf][nf][3] + b1);
            *(float2*)&C[(size_t)m0 * OO + n0] = v0;
            *(float2*)&C[(size_t)(m0 + 8) * OO + n0] = v1;
        }
    }
}

// ---------------- launch ----------------
extern "C" void kernel_launch(void* const* d_in, const int* in_sizes, int n_in,
                              void* d_out, int out_size) {
    const float* x = (const float*)d_in[0];
    const float* W = (const float*)d_in[2];
    const float* b = (const float*)d_in[3];
    float* out = (float*)d_out;

    cudaFuncSetAttribute(gemm_f16_kernel,
                         cudaFuncAttributeMaxDynamicSharedMemorySize, SMEM_TOTAL);

    const int A_GROUPS = NN * (KK / 8);
    const int B_GROUPS = OO * (KK / 8);
    pack_kernel<<<(A_GROUPS + B_GROUPS) / 256, 256>>>(x, W);

    dim3 grid(NN / BM, OO / BN);  // (64, 4) = 256 CTAs, 2/SM, single wave
    gemm_f16_kernel<<<grid, THREADS, SMEM_TOTAL>>>(b, out);
}

// round 10
// speedup vs baseline: 4.2652x; 2.0514x over previous
#include <cuda_runtime.h>
#include <cuda_fp16.h>
#include <cstdint>
#include <math.h>

// out = GELU_exact(x @ W.T + b)
// R10: single-term fp16 mma.sync GEMM; warp tile 64x32 (8 warps / 256 thr),
// 16 independent MMAs per burst, 6:16 ldm4:MMA ratio, occ 2.

#define NN 8192
#define KK 512
#define OO 512

#define BM 128
#define BN 128
#define BK 64                    // fp16 elems per k-tile (128 B/row)
#define NKT (KK / BK)            // 8
#define THREADS 256

// stage: A[128x64 fp16] 16K | B[128x64 fp16] 16K
#define ST_B   16384
#define STAGE  32768
#define NSTAGE 3
#define SMEM_TOTAL (NSTAGE * STAGE)   // 96 KB

__device__ __align__(128) __half g_xh[NN * KK];   // 8 MB
__device__ __align__(128) __half g_wh[OO * KK];   // 0.5 MB

__device__ __forceinline__ uint32_t smem_u32(const void* p) {
    uint32_t a;
    asm("{ .reg .u64 t; cvta.to.shared.u64 t, %1; cvt.u32.u64 %0, t; }" : "=r"(a) : "l"(p));
    return a;
}

#define CP16(dst, src) \
    asm volatile("cp.async.cg.shared.global [%0], [%1], 16;" :: "r"(dst), "l"(src) : "memory")
#define CP_COMMIT() asm volatile("cp.async.commit_group;" ::: "memory")
#define CP_WAIT1()  asm volatile("cp.async.wait_group 1;" ::: "memory")

__device__ __forceinline__ void ldm4(uint32_t* r, uint32_t addr) {
    asm volatile("ldmatrix.sync.aligned.m8n8.x4.shared.b16 {%0,%1,%2,%3}, [%4];"
                 : "=r"(r[0]), "=r"(r[1]), "=r"(r[2]), "=r"(r[3]) : "r"(addr));
}

__device__ __forceinline__ void mma_f16(float* d, const uint32_t* a, const uint32_t* b) {
    asm volatile(
        "mma.sync.aligned.m16n8k16.row.col.f32.f16.f16.f32 "
        "{%0,%1,%2,%3}, {%4,%5,%6,%7}, {%8,%9}, {%0,%1,%2,%3};"
        : "+f"(d[0]), "+f"(d[1]), "+f"(d[2]), "+f"(d[3])
        : "r"(a[0]), "r"(a[1]), "r"(a[2]), "r"(a[3]), "r"(b[0]), "r"(b[1]));
}

// swizzled byte offset in a 128B-row tile: row r, 16B-chunk c (0..7)
__device__ __forceinline__ uint32_t swz8(int r, int c) {
    return (uint32_t)(r * 128 + (((c ^ (r & 7))) << 4));
}

// A&S 7.1.26 erf (abs err 1.5e-7)
__device__ __forceinline__ float gelu_f(float h) {
    float s = h * 0.70710678118654752f;
    float a = fabsf(s);
    float t = __frcp_rn(fmaf(0.3275911f, a, 1.0f));
    float p = fmaf(fmaf(fmaf(fmaf(1.061405429f, t, -1.453152027f), t, 1.421413741f),
                        t, -0.284496736f), t, 0.254829592f) * t;
    float e = __expf(-a * a);
    float erfv = fmaf(-p, e, 1.0f);
    erfv = copysignf(erfv, s);
    return 0.5f * h * (1.0f + erfv);
}

// ---------------- pack kernel: f32 -> fp16 (rne) ----------------
__global__ __launch_bounds__(256) void pack_kernel(const float* __restrict__ x,
                                                   const float* __restrict__ W) {
    const int g = blockIdx.x * 256 + threadIdx.x;
    const int A_GROUPS = NN * (KK / 8);   // 524288
    const float* src;
    __half* dst;
    if (g < A_GROUPS) {
        src = x + (size_t)g * 8;
        dst = g_xh + (size_t)g * 8;
    } else {
        size_t g2 = (size_t)(g - A_GROUPS);
        src = W + g2 * 8;
        dst = g_wh + g2 * 8;
    }
    float4 v0 = *(const float4*)src;
    float4 v1 = *(const float4*)(src + 4);
    uint32_t o[4];
    o[0] = (uint32_t)__half_as_ushort(__float2half_rn(v0.x)) |
           ((uint32_t)__half_as_ushort(__float2half_rn(v0.y)) << 16);
    o[1] = (uint32_t)__half_as_ushort(__float2half_rn(v0.z)) |
           ((uint32_t)__half_as_ushort(__float2half_rn(v0.w)) << 16);
    o[2] = (uint32_t)__half_as_ushort(__float2half_rn(v1.x)) |
           ((uint32_t)__half_as_ushort(__float2half_rn(v1.y)) << 16);
    o[3] = (uint32_t)__half_as_ushort(__float2half_rn(v1.z)) |
           ((uint32_t)__half_as_ushort(__float2half_rn(v1.w)) << 16);
    *(uint4*)dst = make_uint4(o[0], o[1], o[2], o[3]);
}

// ---------------- main GEMM kernel ----------------
__device__ __forceinline__ void load_stage(uint32_t S, int buf, int kt, int mb, int nb, int tid) {
    const uint32_t st = S + buf * STAGE;
    const int kbase = kt * BK;
    // A: 1024 chunk slots (128 rows x 8 chunks); 256 threads -> 4 each
#pragma unroll
    for (int j = 0; j < 4; j++) {
        int q = tid + j * 256;
        int r = q >> 3, c = q & 7;
        size_t so = (size_t)(mb * BM + r) * KK + kbase + c * 8;
        CP16(st + swz8(r, c), (const uint8_t*)(g_xh + so));
    }
    // B: 1024 chunk slots
#pragma unroll
    for (int j = 0; j < 4; j++) {
        int q = tid + j * 256;
        int r = q >> 3, c = q & 7;
        size_t so = (size_t)(nb * BN + r) * KK + kbase + c * 8;
        CP16(st + ST_B + swz8(r, c), (const uint8_t*)(g_wh + so));
    }
    CP_COMMIT();
}

__global__ __launch_bounds__(THREADS, 2)
void gemm_f16_kernel(const float* __restrict__ bias, float* __restrict__ C) {
    extern __shared__ uint8_t smem[];
    const uint32_t S = smem_u32(smem);
    const int tid = threadIdx.x;
    const int l = tid & 31, wid = tid >> 5;
    const int mwarp = wid & 1;   // 2 M-warps of 64 rows
    const int nwarp = wid >> 1;  // 4 N-warps of 32 cols
    const int mb = blockIdx.x, nb = blockIdx.y;

    // ldmatrix lane maps (proven): rows 128B wide
    const int a_r = ((l >> 3) & 1) * 8 + (l & 7);
    const int a_cs = (l >> 4) & 1;
    const int b_n = ((l >> 4) & 1) * 8 + (l & 7);
    const int b_cs = (l >> 3) & 1;

    float acc[4][4][4];   // [mf][nf][frag]
#pragma unroll
    for (int i = 0; i < 4; i++)
#pragma unroll
        for (int j = 0; j < 4; j++)
#pragma unroll
            for (int k = 0; k < 4; k++) acc[i][j][k] = 0.0f;

    load_stage(S, 0, 0, mb, nb, tid);
    load_stage(S, 1, 1, mb, nb, tid);

    for (int kt = 0; kt < NKT; kt++) {
        CP_WAIT1();
        __syncthreads();
        if (kt + 2 < NKT) load_stage(S, (kt + 2) % NSTAGE, kt + 2, mb, nb, tid);
        const uint32_t stg = S + (kt % NSTAGE) * STAGE;

#pragma unroll
        for (int ks = 0; ks < 4; ks++) {           // 4 k16 slices in BK=64
            const int c0 = ks * 2;
            uint32_t A[4][4], B[8];
            // B: 2 ldm4 -> 4 n8 operands
#pragma unroll
            for (int nf2 = 0; nf2 < 2; nf2++)
                ldm4(&B[nf2 * 4], stg + ST_B + swz8(nwarp * 32 + nf2 * 16 + b_n, c0 + b_cs));
            // A: 4 ldm4 -> 4 m16 operands
#pragma unroll
            for (int mf = 0; mf < 4; mf++)
                ldm4(A[mf], stg + swz8(mwarp * 64 + mf * 16 + a_r, c0 + a_cs));
            // 16 independent MMAs
#pragma unroll
            for (int mf = 0; mf < 4; mf++)
#pragma unroll
                for (int nf = 0; nf < 4; nf++)
                    mma_f16(acc[mf][nf], A[mf], &B[nf * 2]);
        }
    }

    // epilogue: bias + GELU
#pragma unroll
    for (int mf = 0; mf < 4; mf++) {
#pragma unroll
        for (int nf = 0; nf < 4; nf++) {
            int m0 = mb * BM + mwarp * 64 + mf * 16 + (l >> 2);
            int n0 = nb * BN + nwarp * 32 + nf * 8 + 2 * (l & 3);
            float b0 = __ldg(&bias[n0]);
            float b1 = __ldg(&bias[n0 + 1]);
            float2 v0, v1;
            v0.x = gelu_f(acc[mf][nf][0] + b0);
            v0.y = gelu_f(acc[mf][nf][1] + b1);
            v1.x = gelu_f(acc[mf][nf][2] + b0);
            v1.y = gelu_f(acc[mf][nf][3] + b1);
            *(float2*)&C[(size_t)m0 * OO + n0] = v0;
            *(float2*)&C[(size_t)(m0 + 8) * OO + n0] = v1;
        }
    }
}

// ---------------- launch ----------------
extern "C" void kernel_launch(void* const* d_in, const int* in_sizes, int n_in,
                              void* d_out, int out_size) {
    const float* x = (const float*)d_in[0];
    const float* W = (const float*)d_in[2];
    const float* b = (const float*)d_in[3];
    float* out = (float*)d_out;

    cudaFuncSetAttribute(gemm_f16_kernel,
                         cudaFuncAttributeMaxDynamicSharedMemorySize, SMEM_TOTAL);

    const int A_GROUPS = NN * (KK / 8);
    const int B_GROUPS = OO * (KK / 8);
    pack_kernel<<<(A_GROUPS + B_GROUPS) / 256, 256>>>(x, W);

    dim3 grid(NN / BM, OO / BN);  // (64, 4) = 256 CTAs, 2/SM, single wave
    gemm_f16_kernel<<<grid, THREADS, SMEM_TOTAL>>>(b, out);
}

// round 11
// speedup vs baseline: 4.3156x; 1.0118x over previous
#include <cuda_runtime.h>
#include <cuda_fp16.h>
#include <cstdint>
#include <math.h>

// out = GELU_exact(x @ W.T + b)
// R11: fp16 single-term mma.sync GEMM. vs R10: all ldmatrix/cp.async address
// math hoisted out of the mainloop (gmem ptrs advance by constant), and B
// fragments double-buffered across k16 slices so MMA bursts cover LDSM latency.

#define NN 8192
#define KK 512
#define OO 512

#define BM 128
#define BN 128
#define BK 64                    // fp16 elems per k-tile (128 B/row)
#define NKT (KK / BK)            // 8
#define THREADS 256

#define ST_B   16384
#define STAGE  32768
#define NSTAGE 3
#define SMEM_TOTAL (NSTAGE * STAGE)   // 96 KB

__device__ __align__(128) __half g_xh[NN * KK];   // 8 MB
__device__ __align__(128) __half g_wh[OO * KK];   // 0.5 MB

__device__ __forceinline__ uint32_t smem_u32(const void* p) {
    uint32_t a;
    asm("{ .reg .u64 t; cvta.to.shared.u64 t, %1; cvt.u32.u64 %0, t; }" : "=r"(a) : "l"(p));
    return a;
}

#define CP16(dst, src) \
    asm volatile("cp.async.cg.shared.global [%0], [%1], 16;" :: "r"(dst), "l"(src) : "memory")
#define CP_COMMIT() asm volatile("cp.async.commit_group;" ::: "memory")
#define CP_WAIT1()  asm volatile("cp.async.wait_group 1;" ::: "memory")

__device__ __forceinline__ void ldm4(uint32_t* r, uint32_t addr) {
    asm volatile("ldmatrix.sync.aligned.m8n8.x4.shared.b16 {%0,%1,%2,%3}, [%4];"
                 : "=r"(r[0]), "=r"(r[1]), "=r"(r[2]), "=r"(r[3]) : "r"(addr));
}

__device__ __forceinline__ void mma_f16(float* d, const uint32_t* a, const uint32_t* b) {
    asm volatile(
        "mma.sync.aligned.m16n8k16.row.col.f32.f16.f16.f32 "
        "{%0,%1,%2,%3}, {%4,%5,%6,%7}, {%8,%9}, {%0,%1,%2,%3};"
        : "+f"(d[0]), "+f"(d[1]), "+f"(d[2]), "+f"(d[3])
        : "r"(a[0]), "r"(a[1]), "r"(a[2]), "r"(a[3]), "r"(b[0]), "r"(b[1]));
}

// swizzled byte offset in a 128B-row tile: row r, 16B-chunk c (0..7)
__device__ __forceinline__ uint32_t swz8(int r, int c) {
    return (uint32_t)(r * 128 + (((c ^ (r & 7))) << 4));
}

// A&S 7.1.26 erf (abs err 1.5e-7)
__device__ __forceinline__ float gelu_f(float h) {
    float s = h * 0.70710678118654752f;
    float a = fabsf(s);
    float t = __frcp_rn(fmaf(0.3275911f, a, 1.0f));
    float p = fmaf(fmaf(fmaf(fmaf(1.061405429f, t, -1.453152027f), t, 1.421413741f),
                        t, -0.284496736f), t, 0.254829592f) * t;
    float e = __expf(-a * a);
    float erfv = fmaf(-p, e, 1.0f);
    erfv = copysignf(erfv, s);
    return 0.5f * h * (1.0f + erfv);
}

// ---------------- pack kernel: f32 -> fp16 (rne) ----------------
__global__ __launch_bounds__(256) void pack_kernel(const float* __restrict__ x,
                                                   const float* __restrict__ W) {
    const int g = blockIdx.x * 256 + threadIdx.x;
    const int A_GROUPS = NN * (KK / 8);
    const float* src;
    __half* dst;
    if (g < A_GROUPS) {
        src = x + (size_t)g * 8;
        dst = g_xh + (size_t)g * 8;
    } else {
        size_t g2 = (size_t)(g - A_GROUPS);
        src = W + g2 * 8;
        dst = g_wh + g2 * 8;
    }
    float4 v0 = *(const float4*)src;
    float4 v1 = *(const float4*)(src + 4);
    uint32_t o[4];
    o[0] = (uint32_t)__half_as_ushort(__float2half_rn(v0.x)) |
           ((uint32_t)__half_as_ushort(__float2half_rn(v0.y)) << 16);
    o[1] = (uint32_t)__half_as_ushort(__float2half_rn(v0.z)) |
           ((uint32_t)__half_as_ushort(__float2half_rn(v0.w)) << 16);
    o[2] = (uint32_t)__half_as_ushort(__float2half_rn(v1.x)) |
           ((uint32_t)__half_as_ushort(__float2half_rn(v1.y)) << 16);
    o[3] = (uint32_t)__half_as_ushort(__float2half_rn(v1.z)) |
           ((uint32_t)__half_as_ushort(__float2half_rn(v1.w)) << 16);
    *(uint4*)dst = make_uint4(o[0], o[1], o[2], o[3]);
}

// ---------------- main GEMM kernel ----------------
__global__ __launch_bounds__(THREADS, 2)
void gemm_f16_kernel(const float* __restrict__ bias, float* __restrict__ C) {
    extern __shared__ uint8_t smem[];
    const uint32_t S = smem_u32(smem);
    const int tid = threadIdx.x;
    const int l = tid & 31, wid = tid >> 5;
    const int mwarp = wid & 1;   // 2 M-warps of 64 rows
    const int nwarp = wid >> 1;  // 4 N-warps of 32 cols
    const int mb = blockIdx.x, nb = blockIdx.y;

    // ---- hoisted loader addressing (thread-constant) ----
    const int lr = tid >> 3, lc = tid & 7;      // loader row 0..31, chunk 0..7
    uint32_t s_dstA[4], s_dstB[4];
    const uint8_t *gA[4], *gB[4];
#pragma unroll
    for (int j = 0; j < 4; j++) {
        int r = lr + j * 32;
        s_dstA[j] = swz8(r, lc);
        s_dstB[j] = ST_B + swz8(r, lc);
        gA[j] = (const uint8_t*)(g_xh + (size_t)(mb * BM + r) * KK + lc * 8);
        gB[j] = (const uint8_t*)(g_wh + (size_t)(nb * BN + r) * KK + lc * 8);
    }
    // per-kt advance: BK halves = 128 bytes

    // ---- hoisted ldmatrix addressing (stage-relative, thread-constant) ----
    const int a_r = ((l >> 3) & 1) * 8 + (l & 7);
    const int a_cs = (l >> 4) & 1;
    const int b_n = ((l >> 4) & 1) * 8 + (l & 7);
    const int b_cs = (l >> 3) & 1;
    uint32_t baseA[4], baseB[2];
#pragma unroll
    for (int mf = 0; mf < 4; mf++) baseA[mf] = swz8(mwarp * 64 + mf * 16 + a_r, a_cs);
#pragma unroll
    for (int nf2 = 0; nf2 < 2; nf2++) baseB[nf2] = ST_B + swz8(nwarp * 32 + nf2 * 16 + b_n, b_cs);
    const uint32_t aXor = (uint32_t)(a_r & 7) << 4;   // for c0^  (bits 5..6 toggled by ks)
    const uint32_t bXor = (uint32_t)(b_n & 7) << 4;
    // slice offset for base addressed at c0=0: addr(ks) = base ^ (ksoff), where
    // ksoff toggles chunk bits 1..2: ((2*ks) << 4) XORed into the chunk field.
    // Since base already contains (cs ^ (r&7)) in the chunk field, XOR with (2*ks)<<4
    // yields exactly swz8(r, 2*ks + cs) (2*ks affects only bits 1-2 of chunk, cs bit 0,
    // r&7 full 3 bits - XOR is correct because 2*ks has bit0 = 0).
    (void)aXor; (void)bXor;

    float acc[4][4][4];
#pragma unroll
    for (int i = 0; i < 4; i++)
#pragma unroll
        for (int j = 0; j < 4; j++)
#pragma unroll
            for (int k = 0; k < 4; k++) acc[i][j][k] = 0.0f;

    // prologue loads: kt 0 and 1
#pragma unroll
    for (int s = 0; s < 2; s++) {
        const uint32_t st = S + s * STAGE;
#pragma unroll
        for (int j = 0; j < 4; j++) {
            CP16(st + s_dstA[j], gA[j] + s * 128);
            CP16(st + s_dstB[j], gB[j] + s * 128);
        }
        CP_COMMIT();
    }

    for (int kt = 0; kt < NKT; kt++) {
        CP_WAIT1();
        __syncthreads();
        if (kt + 2 < NKT) {
            const uint32_t st = S + ((kt + 2) % NSTAGE) * STAGE;
            const uint32_t go = (uint32_t)(kt + 2) * 128;
#pragma unroll
            for (int j = 0; j < 4; j++) {
                CP16(st + s_dstA[j], gA[j] + go);
                CP16(st + s_dstB[j], gB[j] + go);
            }
            CP_COMMIT();
        }
        const uint32_t stg = S + (kt % NSTAGE) * STAGE;

        // B double-buffer across the 4 k16 slices
        uint32_t Bf[2][8], A[4][4];
#pragma unroll
        for (int nf2 = 0; nf2 < 2; nf2++)
            ldm4(&Bf[0][nf2 * 4], stg + (baseB[nf2] ^ 0u));
#pragma unroll
        for (int ks = 0; ks < 4; ks++) {
            const uint32_t ksoff = (uint32_t)(2 * ks) << 4;
            const int cur = ks & 1, nxt = cur ^ 1;
            // prefetch next slice's B
            if (ks < 3) {
                const uint32_t nko = (uint32_t)(2 * (ks + 1)) << 4;
#pragma unroll
                for (int nf2 = 0; nf2 < 2; nf2++)
                    ldm4(&Bf[nxt][nf2 * 4], stg + (baseB[nf2] ^ nko));
            }
            // A fragments for this slice
#pragma unroll
            for (int mf = 0; mf < 4; mf++)
                ldm4(A[mf], stg + (baseA[mf] ^ ksoff));
            // 16 independent MMAs
#pragma unroll
            for (int mf = 0; mf < 4; mf++)
#pragma unroll
                for (int nf = 0; nf < 4; nf++)
                    mma_f16(acc[mf][nf], A[mf], &Bf[cur][nf * 2]);
        }
    }

    // epilogue: bias + GELU
#pragma unroll
    for (int mf = 0; mf < 4; mf++) {
#pragma unroll
        for (int nf = 0; nf < 4; nf++) {
            int m0 = mb * BM + mwarp * 64 + mf * 16 + (l >> 2);
            int n0 = nb * BN + nwarp * 32 + nf * 8 + 2 * (l & 3);
            float b0 = __ldg(&bias[n0]);
            float b1 = __ldg(&bias[n0 + 1]);
            float2 v0, v1;
            v0.x = gelu_f(acc[mf][nf][0] + b0);
            v0.y = gelu_f(acc[mf][nf][1] + b1);
            v1.x = gelu_f(acc[mf][nf][2] + b0);
            v1.y = gelu_f(acc[mf][nf][3] + b1);
            *(float2*)&C[(size_t)m0 * OO + n0] = v0;
            *(float2*)&C[(size_t)(m0 + 8) * OO + n0] = v1;
        }
    }
}

// ---------------- launch ----------------
extern "C" void kernel_launch(void* const* d_in, const int* in_sizes, int n_in,
                              void* d_out, int out_size) {
    const float* x = (const float*)d_in[0];
    const float* W = (const float*)d_in[2];
    const float* b = (const float*)d_in[3];
    float* out = (float*)d_out;

    cudaFuncSetAttribute(gemm_f16_kernel,
                         cudaFuncAttributeMaxDynamicSharedMemorySize, SMEM_TOTAL);

    const int A_GROUPS = NN * (KK / 8);
    const int B_GROUPS = OO * (KK / 8);
    pack_kernel<<<(A_GROUPS + B_GROUPS) / 256, 256>>>(x, W);

    dim3 grid(NN / BM, OO / BN);  // (64, 4) = 256 CTAs, 2/SM, single wave
    gemm_f16_kernel<<<grid, THREADS, SMEM_TOTAL>>>(b, out);
}